// round 6
// baseline (speedup 1.0000x reference)
#include <cuda_runtime.h>

#define B_TOTAL 8192
#define H_      200
#define G4      800     // 4*H
#define T_      100
#define OUTC    400     // SEQ_LEN*NUM_AXIS
#define TILE_B  64
#define NCTA    (B_TOTAL / TILE_B)   // 128
#define NTHREADS 800                 // 16 b-groups * 50 j-groups (25 warps)
#define JGROUPS  50

// Cell-state scratch (allocation-free rule: __device__ global array). 19.66 MB, L2-resident.
__device__ float g_c[(size_t)3 * B_TOTAL * H_];

typedef unsigned long long u64;

__device__ __forceinline__ u64 pack2(float x, float y) {
    u64 r; asm("mov.b64 %0, {%1, %2};" : "=l"(r) : "f"(x), "f"(y)); return r;
}
__device__ __forceinline__ float2 unpack2(u64 v) {
    float2 f; asm("mov.b64 {%0, %1}, %2;" : "=f"(f.x), "=f"(f.y) : "l"(v)); return f;
}
// Packed f32x2 FMA (Blackwell): 2 fp32 MACs per instruction slot.
__device__ __forceinline__ void fma2(u64& acc, u64 a, u64 b) {
    asm("fma.rn.f32x2 %0, %1, %2, %0;" : "+l"(acc) : "l"(a), "l"(b));
}

__device__ __forceinline__ float sigm_(float x) { return 1.0f / (1.0f + __expf(-x)); }
__device__ __forceinline__ float tanh_(float x) {
    float e = __expf(-2.0f * fabsf(x));
    float r = (1.0f - e) / (1.0f + e);
    return copysignf(r, x);
}

// acc[b][jpair] += hsm[k][b0+b] * Wp[k*LD + (0..3)]  for k in [0,200)
// Wp points at (weight base + gate*H + j0); hsm is k-major [200][TILE_B] in smem.
template<int LD>
__device__ __forceinline__ void mm_accum(u64 acc[4][2],
        const float* __restrict__ Wp, const float* hsm, int b0)
{
#pragma unroll 4
    for (int k = 0; k < H_; ++k) {
        float4 wv = *reinterpret_cast<const float4*>(Wp + k * LD);
        float4 hv = *reinterpret_cast<const float4*>(hsm + k * TILE_B + b0);
        u64 w01 = pack2(wv.x, wv.y);
        u64 w23 = pack2(wv.z, wv.w);
        u64 hh;
        hh = pack2(hv.x, hv.x); fma2(acc[0][0], w01, hh); fma2(acc[0][1], w23, hh);
        hh = pack2(hv.y, hv.y); fma2(acc[1][0], w01, hh); fma2(acc[1][1], w23, hh);
        hh = pack2(hv.z, hv.z); fma2(acc[2][0], w01, hh); fma2(acc[2][1], w23, hh);
        hh = pack2(hv.w, hv.w); fma2(acc[3][0], w01, hh); fma2(acc[3][1], w23, hh);
    }
}

// One gate's pre-activation z[b][j] for the thread's 4b x 4j tile.
// gate: 0=i, 1=f, 2=g, 3=o.  z = bias + (layer0 ? x*W0row : hin@W) + hrec@U
__device__ __forceinline__ void gate4(
    float g[4][4], int gate,
    const float* __restrict__ W, const float* __restrict__ U,
    const float* __restrict__ bias,
    const float* hin, const float* hrec, const float* xbuf,
    int b0, int j0, bool layer0)
{
    u64 acc[4][2];
    float4 bv = *reinterpret_cast<const float4*>(bias + gate * H_ + j0);
    u64 b01 = pack2(bv.x, bv.y), b23 = pack2(bv.z, bv.w);
#pragma unroll
    for (int b = 0; b < 4; ++b) { acc[b][0] = b01; acc[b][1] = b23; }

    if (layer0) {
        // input dim 1: z += x[b] * W0[0][col]
        float4 wv = *reinterpret_cast<const float4*>(W + gate * H_ + j0);
        u64 w01 = pack2(wv.x, wv.y), w23 = pack2(wv.z, wv.w);
        float4 xv = *reinterpret_cast<const float4*>(xbuf + b0);
        u64 hh;
        hh = pack2(xv.x, xv.x); fma2(acc[0][0], w01, hh); fma2(acc[0][1], w23, hh);
        hh = pack2(xv.y, xv.y); fma2(acc[1][0], w01, hh); fma2(acc[1][1], w23, hh);
        hh = pack2(xv.z, xv.z); fma2(acc[2][0], w01, hh); fma2(acc[2][1], w23, hh);
        hh = pack2(xv.w, xv.w); fma2(acc[3][0], w01, hh); fma2(acc[3][1], w23, hh);
    } else {
        mm_accum<G4>(acc, W + gate * H_ + j0, hin, b0);
    }
    mm_accum<G4>(acc, U + gate * H_ + j0, hrec, b0);

#pragma unroll
    for (int b = 0; b < 4; ++b) {
        float2 p0 = unpack2(acc[b][0]), p1 = unpack2(acc[b][1]);
        g[b][0] = p0.x; g[b][1] = p0.y; g[b][2] = p1.x; g[b][3] = p1.y;
    }
}

__device__ __forceinline__ void lstm_layer(
    int t,
    const float* __restrict__ W, const float* __restrict__ U,
    const float* __restrict__ bias,
    const float* hin, float* hrec, const float* xbuf,
    float* __restrict__ cptr,   // c state for this CTA's batch tile: [TILE_B][H_]
    int b0, int j0, bool layer0)
{
    // Phase f: cnew = sigmoid(f) * c_old
    float fg[4][4];
    gate4(fg, 1, W, U, bias, hin, hrec, xbuf, b0, j0, layer0);
    float cnew[4][4];
#pragma unroll
    for (int b = 0; b < 4; ++b) {
        float4 c4 = make_float4(0.f, 0.f, 0.f, 0.f);
        if (t > 0) c4 = *reinterpret_cast<const float4*>(cptr + (b0 + b) * H_ + j0);
        cnew[b][0] = sigm_(fg[b][0]) * c4.x;
        cnew[b][1] = sigm_(fg[b][1]) * c4.y;
        cnew[b][2] = sigm_(fg[b][2]) * c4.z;
        cnew[b][3] = sigm_(fg[b][3]) * c4.w;
    }
    // Phase i
    float iv[4][4];
    gate4(iv, 0, W, U, bias, hin, hrec, xbuf, b0, j0, layer0);
#pragma unroll
    for (int b = 0; b < 4; ++b)
#pragma unroll
        for (int j = 0; j < 4; ++j) iv[b][j] = sigm_(iv[b][j]);
    // Phase g: cnew += sigmoid(i)*tanh(g); store c
    {
        float gg[4][4];
        gate4(gg, 2, W, U, bias, hin, hrec, xbuf, b0, j0, layer0);
#pragma unroll
        for (int b = 0; b < 4; ++b) {
#pragma unroll
            for (int j = 0; j < 4; ++j) cnew[b][j] += iv[b][j] * tanh_(gg[b][j]);
            *reinterpret_cast<float4*>(cptr + (b0 + b) * H_ + j0) =
                make_float4(cnew[b][0], cnew[b][1], cnew[b][2], cnew[b][3]);
        }
    }
    // Phase o: h = sigmoid(o) * tanh(cnew)
    float og[4][4];
    gate4(og, 3, W, U, bias, hin, hrec, xbuf, b0, j0, layer0);
    float hnew[4][4];
#pragma unroll
    for (int b = 0; b < 4; ++b)
#pragma unroll
        for (int j = 0; j < 4; ++j) hnew[b][j] = sigm_(og[b][j]) * tanh_(cnew[b][j]);

    __syncthreads();   // all reads of old hrec done
#pragma unroll
    for (int j = 0; j < 4; ++j) {
        *reinterpret_cast<float4*>(hrec + (j0 + j) * TILE_B + b0) =
            make_float4(hnew[0][j], hnew[1][j], hnew[2][j], hnew[3][j]);
    }
    __syncthreads();   // new hrec visible
}

__global__ void __launch_bounds__(NTHREADS, 1) lstm3_kernel(
    const float* __restrict__ x,
    const float* __restrict__ W0, const float* __restrict__ U0, const float* __restrict__ b0v,
    const float* __restrict__ W1, const float* __restrict__ U1, const float* __restrict__ b1v,
    const float* __restrict__ W2, const float* __restrict__ U2, const float* __restrict__ b2v,
    const float* __restrict__ Wfc, const float* __restrict__ bfc,
    float* __restrict__ out)
{
    extern __shared__ float sm[];
    float* hs0  = sm;                       // [H_][TILE_B] k-major
    float* hs1  = sm + H_ * TILE_B;
    float* hs2  = sm + 2 * H_ * TILE_B;
    float* xbuf = sm + 3 * H_ * TILE_B;     // [TILE_B]

    const int tid   = threadIdx.x;
    const int bbase = blockIdx.x * TILE_B;
    const int bg = tid / JGROUPS, jg = tid % JGROUPS;
    const int b0 = bg * 4, j0 = jg * 4;

    for (int i = tid; i < 3 * H_ * TILE_B; i += NTHREADS) sm[i] = 0.0f;
    __syncthreads();

    float* c0 = g_c + ((size_t)0 * B_TOTAL + bbase) * H_;
    float* c1 = g_c + ((size_t)1 * B_TOTAL + bbase) * H_;
    float* c2 = g_c + ((size_t)2 * B_TOTAL + bbase) * H_;

    for (int t = 0; t < T_; ++t) {
        if (tid < TILE_B) xbuf[tid] = x[(size_t)(bbase + tid) * T_ + t];
        __syncthreads();
        lstm_layer(t, W0, U0, b0v, nullptr, hs0, xbuf, c0, b0, j0, true);
        lstm_layer(t, W1, U1, b1v, hs0,    hs1, xbuf, c1, b0, j0, false);
        lstm_layer(t, W2, U2, b2v, hs1,    hs2, xbuf, c2, b0, j0, false);
    }

    // Dense head: y[b][m] = tanh(h2[b] @ Wfc[:,m] + bfc[m]),  m in [0,400)
#pragma unroll
    for (int pass = 0; pass < 2; ++pass) {
        const int m0 = pass * H_ + j0;   // covers [0,200) then [200,400)
        u64 acc[4][2];
        float4 bv = *reinterpret_cast<const float4*>(bfc + m0);
        u64 p01 = pack2(bv.x, bv.y), p23 = pack2(bv.z, bv.w);
#pragma unroll
        for (int b = 0; b < 4; ++b) { acc[b][0] = p01; acc[b][1] = p23; }
        mm_accum<OUTC>(acc, Wfc + m0, hs2, b0);
#pragma unroll
        for (int b = 0; b < 4; ++b) {
            float2 q0 = unpack2(acc[b][0]), q1 = unpack2(acc[b][1]);
            float4 y = make_float4(tanh_(q0.x), tanh_(q0.y), tanh_(q1.x), tanh_(q1.y));
            *reinterpret_cast<float4*>(out + (size_t)(bbase + b0 + b) * OUTC + m0) = y;
        }
    }
}

extern "C" void kernel_launch(void* const* d_in, const int* in_sizes, int n_in,
                              void* d_out, int out_size) {
    (void)in_sizes; (void)n_in; (void)out_size;
    const float* x   = (const float*)d_in[0];
    const float* W0  = (const float*)d_in[1];
    const float* U0  = (const float*)d_in[2];
    const float* b0v = (const float*)d_in[3];
    const float* W1  = (const float*)d_in[4];
    const float* U1  = (const float*)d_in[5];
    const float* b1v = (const float*)d_in[6];
    const float* W2  = (const float*)d_in[7];
    const float* U2  = (const float*)d_in[8];
    const float* b2v = (const float*)d_in[9];
    const float* Wfc = (const float*)d_in[10];
    const float* bfc = (const float*)d_in[11];
    float* out = (float*)d_out;

    const int smem_bytes = (3 * H_ * TILE_B + TILE_B) * (int)sizeof(float);  // 153,856 B
    cudaFuncSetAttribute(lstm3_kernel, cudaFuncAttributeMaxDynamicSharedMemorySize, smem_bytes);
    lstm3_kernel<<<NCTA, NTHREADS, smem_bytes>>>(
        x, W0, U0, b0v, W1, U1, b1v, W2, U2, b2v, Wfc, bfc, out);
}

// round 7
// speedup vs baseline: 1.5976x; 1.5976x over previous
#include <cuda_runtime.h>

#define B_TOTAL 8192
#define H_      200
#define G4      800     // 4*H
#define T_      100
#define OUTC    400     // SEQ_LEN*NUM_AXIS
#define TILE_B  64
#define NCTA    (B_TOTAL / TILE_B)   // 128
#define NTHREADS 800                 // 16 b-groups * 50 j-groups (25 warps)
#define JGROUPS  50

// Cell-state scratch (allocation-free rule: __device__ global array). 19.66 MB, L2-resident.
__device__ float g_c[(size_t)3 * B_TOTAL * H_];

typedef unsigned long long u64;

__device__ __forceinline__ u64 pack2(float x, float y) {
    u64 r; asm("mov.b64 %0, {%1, %2};" : "=l"(r) : "f"(x), "f"(y)); return r;
}
__device__ __forceinline__ float2 unpack2(u64 v) {
    float2 f; asm("mov.b64 {%0, %1}, %2;" : "=f"(f.x), "=f"(f.y) : "l"(v)); return f;
}
// Packed f32x2 FMA (Blackwell): 2 fp32 MACs per instruction slot.
__device__ __forceinline__ void fma2(u64& acc, u64 a, u64 b) {
    asm("fma.rn.f32x2 %0, %1, %2, %0;" : "+l"(acc) : "l"(a), "l"(b));
}

__device__ __forceinline__ float sigm_(float x) { return 1.0f / (1.0f + __expf(-x)); }
__device__ __forceinline__ float tanh_(float x) {
    float e = __expf(-2.0f * fabsf(x));
    float r = (1.0f - e) / (1.0f + e);
    return copysignf(r, x);
}

// acc[b][jpair] += hsm[k][b0+b] * Wp[k*LD + (0..3)]  for k in [0,200)
// Wp points at (weight base + gate*H + j0); hsm is k-major [200][TILE_B] in smem.
template<int LD>
__device__ __forceinline__ void mm_accum(u64 acc[4][2],
        const float* __restrict__ Wp, const float* hsm, int b0)
{
#pragma unroll 4
    for (int k = 0; k < H_; ++k) {
        float4 wv = *reinterpret_cast<const float4*>(Wp + k * LD);
        float4 hv = *reinterpret_cast<const float4*>(hsm + k * TILE_B + b0);
        u64 w01 = pack2(wv.x, wv.y);
        u64 w23 = pack2(wv.z, wv.w);
        u64 hh;
        hh = pack2(hv.x, hv.x); fma2(acc[0][0], w01, hh); fma2(acc[0][1], w23, hh);
        hh = pack2(hv.y, hv.y); fma2(acc[1][0], w01, hh); fma2(acc[1][1], w23, hh);
        hh = pack2(hv.z, hv.z); fma2(acc[2][0], w01, hh); fma2(acc[2][1], w23, hh);
        hh = pack2(hv.w, hv.w); fma2(acc[3][0], w01, hh); fma2(acc[3][1], w23, hh);
    }
}

// One gate's pre-activation z[b][j] for the thread's 4b x 4j tile.
// gate: 0=i, 1=f, 2=g, 3=o.  z = bias + (layer0 ? x*W0row : hin@W) + hrec@U
__device__ __forceinline__ void gate4(
    float g[4][4], int gate,
    const float* __restrict__ W, const float* __restrict__ U,
    const float* __restrict__ bias,
    const float* hin, const float* hrec, const float* xbuf,
    int b0, int j0, bool layer0)
{
    u64 acc[4][2];
    float4 bv = *reinterpret_cast<const float4*>(bias + gate * H_ + j0);
    u64 b01 = pack2(bv.x, bv.y), b23 = pack2(bv.z, bv.w);
#pragma unroll
    for (int b = 0; b < 4; ++b) { acc[b][0] = b01; acc[b][1] = b23; }

    if (layer0) {
        // input dim 1: z += x[b] * W0[0][col]
        float4 wv = *reinterpret_cast<const float4*>(W + gate * H_ + j0);
        u64 w01 = pack2(wv.x, wv.y), w23 = pack2(wv.z, wv.w);
        float4 xv = *reinterpret_cast<const float4*>(xbuf + b0);
        u64 hh;
        hh = pack2(xv.x, xv.x); fma2(acc[0][0], w01, hh); fma2(acc[0][1], w23, hh);
        hh = pack2(xv.y, xv.y); fma2(acc[1][0], w01, hh); fma2(acc[1][1], w23, hh);
        hh = pack2(xv.z, xv.z); fma2(acc[2][0], w01, hh); fma2(acc[2][1], w23, hh);
        hh = pack2(xv.w, xv.w); fma2(acc[3][0], w01, hh); fma2(acc[3][1], w23, hh);
    } else {
        mm_accum<G4>(acc, W + gate * H_ + j0, hin, b0);
    }
    mm_accum<G4>(acc, U + gate * H_ + j0, hrec, b0);

#pragma unroll
    for (int b = 0; b < 4; ++b) {
        float2 p0 = unpack2(acc[b][0]), p1 = unpack2(acc[b][1]);
        g[b][0] = p0.x; g[b][1] = p0.y; g[b][2] = p1.x; g[b][3] = p1.y;
    }
}

__device__ __forceinline__ void lstm_layer(
    int t,
    const float* __restrict__ W, const float* __restrict__ U,
    const float* __restrict__ bias,
    const float* hin, float* hrec, const float* xbuf,
    float* __restrict__ cptr,   // c state for this CTA's batch tile: [TILE_B][H_]
    int b0, int j0, bool layer0)
{
    // Phase f: cnew = sigmoid(f) * c_old
    float fg[4][4];
    gate4(fg, 1, W, U, bias, hin, hrec, xbuf, b0, j0, layer0);
    float cnew[4][4];
#pragma unroll
    for (int b = 0; b < 4; ++b) {
        float4 c4 = make_float4(0.f, 0.f, 0.f, 0.f);
        if (t > 0) c4 = *reinterpret_cast<const float4*>(cptr + (b0 + b) * H_ + j0);
        cnew[b][0] = sigm_(fg[b][0]) * c4.x;
        cnew[b][1] = sigm_(fg[b][1]) * c4.y;
        cnew[b][2] = sigm_(fg[b][2]) * c4.z;
        cnew[b][3] = sigm_(fg[b][3]) * c4.w;
    }
    // Phase i
    float iv[4][4];
    gate4(iv, 0, W, U, bias, hin, hrec, xbuf, b0, j0, layer0);
#pragma unroll
    for (int b = 0; b < 4; ++b)
#pragma unroll
        for (int j = 0; j < 4; ++j) iv[b][j] = sigm_(iv[b][j]);
    // Phase g: cnew += sigmoid(i)*tanh(g); store c
    {
        float gg[4][4];
        gate4(gg, 2, W, U, bias, hin, hrec, xbuf, b0, j0, layer0);
#pragma unroll
        for (int b = 0; b < 4; ++b) {
#pragma unroll
            for (int j = 0; j < 4; ++j) cnew[b][j] += iv[b][j] * tanh_(gg[b][j]);
            *reinterpret_cast<float4*>(cptr + (b0 + b) * H_ + j0) =
                make_float4(cnew[b][0], cnew[b][1], cnew[b][2], cnew[b][3]);
        }
    }
    // Phase o: h = sigmoid(o) * tanh(cnew)
    float og[4][4];
    gate4(og, 3, W, U, bias, hin, hrec, xbuf, b0, j0, layer0);
    float hnew[4][4];
#pragma unroll
    for (int b = 0; b < 4; ++b)
#pragma unroll
        for (int j = 0; j < 4; ++j) hnew[b][j] = sigm_(og[b][j]) * tanh_(cnew[b][j]);

    __syncthreads();   // all reads of old hrec done
#pragma unroll
    for (int j = 0; j < 4; ++j) {
        *reinterpret_cast<float4*>(hrec + (j0 + j) * TILE_B + b0) =
            make_float4(hnew[0][j], hnew[1][j], hnew[2][j], hnew[3][j]);
    }
    __syncthreads();   // new hrec visible
}

__global__ void __launch_bounds__(NTHREADS, 1) lstm3_kernel(
    const float* __restrict__ x,
    const float* __restrict__ W0, const float* __restrict__ U0, const float* __restrict__ b0v,
    const float* __restrict__ W1, const float* __restrict__ U1, const float* __restrict__ b1v,
    const float* __restrict__ W2, const float* __restrict__ U2, const float* __restrict__ b2v,
    const float* __restrict__ Wfc, const float* __restrict__ bfc,
    float* __restrict__ out)
{
    extern __shared__ float sm[];
    float* hs0  = sm;                       // [H_][TILE_B] k-major
    float* hs1  = sm + H_ * TILE_B;
    float* hs2  = sm + 2 * H_ * TILE_B;
    float* xbuf = sm + 3 * H_ * TILE_B;     // [TILE_B]

    const int tid   = threadIdx.x;
    const int bbase = blockIdx.x * TILE_B;
    const int bg = tid / JGROUPS, jg = tid % JGROUPS;
    const int b0 = bg * 4, j0 = jg * 4;

    for (int i = tid; i < 3 * H_ * TILE_B; i += NTHREADS) sm[i] = 0.0f;
    __syncthreads();

    float* c0 = g_c + ((size_t)0 * B_TOTAL + bbase) * H_;
    float* c1 = g_c + ((size_t)1 * B_TOTAL + bbase) * H_;
    float* c2 = g_c + ((size_t)2 * B_TOTAL + bbase) * H_;

    for (int t = 0; t < T_; ++t) {
        if (tid < TILE_B) xbuf[tid] = x[(size_t)(bbase + tid) * T_ + t];
        __syncthreads();
        lstm_layer(t, W0, U0, b0v, nullptr, hs0, xbuf, c0, b0, j0, true);
        lstm_layer(t, W1, U1, b1v, hs0,    hs1, xbuf, c1, b0, j0, false);
        lstm_layer(t, W2, U2, b2v, hs1,    hs2, xbuf, c2, b0, j0, false);
    }

    // Dense head: y[b][m] = tanh(h2[b] @ Wfc[:,m] + bfc[m]),  m in [0,400)
#pragma unroll
    for (int pass = 0; pass < 2; ++pass) {
        const int m0 = pass * H_ + j0;   // covers [0,200) then [200,400)
        u64 acc[4][2];
        float4 bv = *reinterpret_cast<const float4*>(bfc + m0);
        u64 p01 = pack2(bv.x, bv.y), p23 = pack2(bv.z, bv.w);
#pragma unroll
        for (int b = 0; b < 4; ++b) { acc[b][0] = p01; acc[b][1] = p23; }
        mm_accum<OUTC>(acc, Wfc + m0, hs2, b0);
#pragma unroll
        for (int b = 0; b < 4; ++b) {
            float2 q0 = unpack2(acc[b][0]), q1 = unpack2(acc[b][1]);
            float4 y = make_float4(tanh_(q0.x), tanh_(q0.y), tanh_(q1.x), tanh_(q1.y));
            *reinterpret_cast<float4*>(out + (size_t)(bbase + b0 + b) * OUTC + m0) = y;
        }
    }
}

extern "C" void kernel_launch(void* const* d_in, const int* in_sizes, int n_in,
                              void* d_out, int out_size) {
    (void)in_sizes; (void)n_in; (void)out_size;
    const float* x   = (const float*)d_in[0];
    const float* W0  = (const float*)d_in[1];
    const float* U0  = (const float*)d_in[2];
    const float* b0v = (const float*)d_in[3];
    const float* W1  = (const float*)d_in[4];
    const float* U1  = (const float*)d_in[5];
    const float* b1v = (const float*)d_in[6];
    const float* W2  = (const float*)d_in[7];
    const float* U2  = (const float*)d_in[8];
    const float* b2v = (const float*)d_in[9];
    const float* Wfc = (const float*)d_in[10];
    const float* bfc = (const float*)d_in[11];
    float* out = (float*)d_out;

    const int smem_bytes = (3 * H_ * TILE_B + TILE_B) * (int)sizeof(float);  // 153,856 B
    cudaFuncSetAttribute(lstm3_kernel, cudaFuncAttributeMaxDynamicSharedMemorySize, smem_bytes);
    lstm3_kernel<<<NCTA, NTHREADS, smem_bytes>>>(
        x, W0, U0, b0v, W1, U1, b1v, W2, U2, b2v, Wfc, bfc, out);
}